// round 14
// baseline (speedup 1.0000x reference)
#include <cuda_runtime.h>
#include <cuda_fp16.h>
#include <cstdint>
#include <math.h>

#define SS 256
#define BB 64
#define HH 1024
#define VV 8192

// ---------------- scratch (device globals; no allocations allowed) ----------
__device__ float g_emb[SS * BB * HH];          // (S,B,H) embeddings + biases
__device__ float g_wih_t[VV * HH];             // W_ih^T: [v][h]
__device__ float g_hN[BB * HH];                // final hidden state fp32 [b][h]
__device__ __half g_h0[BB * HH];               // initial state fp16 [b][h]
__device__ int   g_isI64;
__device__ unsigned int g_ctr4[4 * 32];        // per-b-group counters, 128B apart

// fp16 GEMM images (K' = 1024):
__device__ __half g_a[(size_t)16384 * 1024];   // h fp16 [m=s*64+b][k]; rnn writes, fc reads
__device__ __half g_b[(size_t)8192 * 1024];    // fc_W fp16

typedef unsigned long long u64;

__device__ __forceinline__ uint32_t smem_u32(const void* p) {
    uint32_t a;
    asm("{ .reg .u64 t; cvta.to.shared.u64 t, %1; cvt.u32.u64 %0, t; }" : "=r"(a) : "l"(p));
    return a;
}
__device__ __forceinline__ unsigned pack_h2(float a, float b) {
    __half2 t = __floats2half2_rn(a, b);
    unsigned u;
    memcpy(&u, &t, 4);
    return u;
}
__device__ __forceinline__ void cpasync16(uint32_t dst, const void* src) {
    asm volatile("cp.async.cg.shared.global [%0], [%1], 16;" :: "r"(dst), "l"(src) : "memory");
}
#define CP_COMMIT() asm volatile("cp.async.commit_group;" ::: "memory")
#define CP_WAIT(n)  asm volatile("cp.async.wait_group %0;" :: "n"(n) : "memory")

__device__ __forceinline__ void ldsm4(uint32_t* r, uint32_t addr) {
    asm volatile("ldmatrix.sync.aligned.m8n8.x4.shared.b16 {%0,%1,%2,%3}, [%4];"
                 : "=r"(r[0]), "=r"(r[1]), "=r"(r[2]), "=r"(r[3]) : "r"(addr));
}
__device__ __forceinline__ void mma16816(float* c, const uint32_t* a, const uint32_t* b) {
    asm volatile(
        "mma.sync.aligned.m16n8k16.row.col.f32.f16.f16.f32 "
        "{%0,%1,%2,%3}, {%4,%5,%6,%7}, {%8,%9}, {%0,%1,%2,%3};"
        : "+f"(c[0]), "+f"(c[1]), "+f"(c[2]), "+f"(c[3])
        : "r"(a[0]), "r"(a[1]), "r"(a[2]), "r"(a[3]), "r"(b[0]), "r"(b[1]));
}
__device__ __forceinline__ unsigned ld_acq(const unsigned int* p) {
    unsigned v;
    asm volatile("ld.acquire.gpu.global.u32 %0, [%1];" : "=r"(v) : "l"(p) : "memory");
    return v;
}

// ---------------- dtype detection --------------------------------------------
__global__ void detect_k(const unsigned int* __restrict__ xw) {
    __shared__ unsigned int red[256];
    unsigned int v = 0;
    for (int i = threadIdx.x; i < 8192; i += 256) v |= xw[2 * i + 1];
    red[threadIdx.x] = v;
    __syncthreads();
    for (int st = 128; st > 0; st >>= 1) {
        if (threadIdx.x < st) red[threadIdx.x] |= red[threadIdx.x + st];
        __syncthreads();
    }
    if (threadIdx.x == 0) g_isI64 = (red[0] == 0u) ? 1 : 0;
}

// ---------------- W_ih transpose ----------------------------------------------
__global__ void transpose_k(const float* __restrict__ in) {
    __shared__ float t[32][33];
    const int R = HH, C = VV;
    int c0 = blockIdx.x * 32, r0 = blockIdx.y * 32;
#pragma unroll
    for (int i = 0; i < 32; i += 8)
        t[threadIdx.y + i][threadIdx.x] =
            in[(size_t)(r0 + threadIdx.y + i) * C + c0 + threadIdx.x];
    __syncthreads();
#pragma unroll
    for (int i = 0; i < 32; i += 8)
        g_wih_t[(size_t)(c0 + threadIdx.y + i) * R + r0 + threadIdx.x] =
            t[threadIdx.x][threadIdx.y + i];
}

// ---------------- init ----------------------------------------------------------
__global__ void st0_k(const float* __restrict__ state) {
    int j = blockIdx.x * 256 + threadIdx.x;
    if (j < BB * HH) g_h0[j] = __float2half_rn(state[j]);
    if (j < 4 * 32) g_ctr4[j] = 0u;
}

// ---------------- embedding gather + bias fold --------------------------------
__global__ void embed_k(const void* __restrict__ xraw,
                        const float* __restrict__ b_ih,
                        const float* __restrict__ b_hh) {
    int sb = blockIdx.x;
    int b = sb & (BB - 1);
    int s = sb >> 6;
    const int* xi = (const int*)xraw;
    long long pos = (long long)b * SS + s;
    int idx = g_isI64 ? xi[2 * pos] : xi[pos];
    int h4 = threadIdx.x * 4;
    float4 w  = *(const float4*)(g_wih_t + (size_t)idx * HH + h4);
    float4 bi = *(const float4*)(b_ih + h4);
    float4 bh = *(const float4*)(b_hh + h4);
    float4 o;
    o.x = w.x + bi.x + bh.x;
    o.y = w.y + bi.y + bh.y;
    o.z = w.z + bi.z + bh.z;
    o.w = w.w + bi.w + bh.w;
    *(float4*)(g_emb + (size_t)sb * HH + h4) = o;
}

// ---------------- conv_w: fc_W -> B fp16 ---------------------------------------
__global__ void conv_w_k(const float* __restrict__ fcW) {
    const int v = blockIdx.x;
    const int t = threadIdx.x;
    const float4* s4 = (const float4*)(fcW + (size_t)v * HH + t * 8);
    float4 va = s4[0], vb = s4[1];
    unsigned hx[4];
    hx[0] = pack_h2(va.x, va.y);
    hx[1] = pack_h2(va.z, va.w);
    hx[2] = pack_h2(vb.x, vb.y);
    hx[3] = pack_h2(vb.z, vb.w);
    *(uint4*)(g_b + (size_t)v * 1024 + t * 8) = make_uint4(hx[0], hx[1], hx[2], hx[3]);
}

// ---------------- persistent recurrence via tensor cores (R12 + lean sync) ----
// 128 CTAs = 4 b-groups(16b=M) x 32 n-blocks(32n=N), 256 threads = 8 warps.
// Per step: distributed counter poll (no bar), cp.async A, mma k-split,
// smem reduce, tanh, g_a store; 2 bar.sync per step.
#define RNN_SW_B  66048
#define RNN_SA_B  34816
#define RNN_SR_F  (8 * 528)
#define RNN_SMEM  (RNN_SW_B + RNN_SA_B + RNN_SR_F * 4)

__global__ void __launch_bounds__(256, 1) rnn_mma_k(const float* __restrict__ W_hh) {
    extern __shared__ char smraw[];
    const uint32_t sW0 = smem_u32(smraw);
    const uint32_t sA0 = sW0 + RNN_SW_B;
    float* sR = (float*)(smraw + RNN_SW_B + RNN_SA_B);

    const int tid = threadIdx.x, cta = blockIdx.x;
    const int lane = tid & 31;
    const int kh   = tid >> 5;
    const int bi = cta >> 5;
    const int n0 = (cta & 31) * 32;
    const int bbase = bi * 16;
    const unsigned int* myctr = &g_ctr4[bi * 32];

    {
        int nrow = tid >> 3, kseg = (tid & 7) * 128;
        const float* wsrc = W_hh + (size_t)(n0 + nrow) * HH + kseg;
        uint32_t wdst = sW0 + (uint32_t)nrow * 2064 + (uint32_t)kseg * 2;
#pragma unroll
        for (int j = 0; j < 16; j++) {
            float4 w1 = *(const float4*)(wsrc + j * 8);
            float4 w2 = *(const float4*)(wsrc + j * 8 + 4);
            uint4 hv = make_uint4(pack_h2(w1.x, w1.y), pack_h2(w1.z, w1.w),
                                  pack_h2(w2.x, w2.y), pack_h2(w2.z, w2.w));
            asm volatile("st.shared.v4.b32 [%0], {%1,%2,%3,%4};"
                         :: "r"(wdst + j * 16), "r"(hv.x), "r"(hv.y), "r"(hv.z), "r"(hv.w)
                         : "memory");
        }
    }
    __syncthreads();

    const int arow = lane & 15;
    const int agq  = lane >> 4;
    const int brow = (lane & 7) + ((lane >> 4) << 3);
    const int bgq  = (lane >> 3) & 1;
    const uint32_t sAw = sA0 + (uint32_t)kh * 4352;

    const int c_b = lane >> 2;
    const int c_n = 2 * (lane & 3);

    const int rn = tid >> 3;
    const int rb = (tid & 7) * 2;
    const int en = n0 + rn;
    const int eb = bbase + rb;

    for (int s = 0; s < SS; s++) {
        // emb prefetch (counter-independent)
        const float* es = g_emb + (size_t)s * BB * HH;
        float e0 = es[(size_t)eb * HH + en];
        float e1 = es[(size_t)(eb + 1) * HH + en];

        // distributed poll: all threads wait until step s inputs are published
        if (s > 0) {
            unsigned target = 32u * (unsigned)s;
            while (ld_acq(myctr) < target) { }
        }

        const __half* hsrc = (s == 0) ? (g_h0 + (size_t)bbase * HH)
                                      : (g_a + ((size_t)(s - 1) * 64 + bbase) * 1024);
#pragma unroll
        for (int i = 0; i < 8; i++) {
            int id = i * 32 + lane;
            int row = id >> 4, c16 = id & 15;
            cpasync16(sAw + (uint32_t)(row * 272 + c16 * 16),
                      hsrc + (size_t)row * 1024 + kh * 128 + c16 * 8);
        }
        CP_COMMIT();
        CP_WAIT(0);
        __syncwarp();

        float acc[4][4];
#pragma unroll
        for (int i = 0; i < 4; i++)
#pragma unroll
            for (int q = 0; q < 4; q++) acc[i][q] = 0.0f;

#pragma unroll
        for (int kt = 0; kt < 8; kt++) {
            uint32_t afr[4], bfr[2][4];
            ldsm4(afr, sAw + (uint32_t)(arow * 272 + kt * 32 + agq * 16));
#pragma unroll
            for (int bt = 0; bt < 2; bt++)
                ldsm4(bfr[bt], sW0 + (uint32_t)((brow + bt * 16) * 2064
                                                + kh * 256 + kt * 32 + bgq * 16));
#pragma unroll
            for (int nt = 0; nt < 4; nt++)
                mma16816(acc[nt], afr, &bfr[nt >> 1][(nt & 1) * 2]);
        }

        float* rw = sR + kh * 528;
#pragma unroll
        for (int nt = 0; nt < 4; nt++) {
            int n = nt * 8 + c_n;
            rw[c_b * 33 + n]           = acc[nt][0];
            rw[c_b * 33 + n + 1]       = acc[nt][1];
            rw[(c_b + 8) * 33 + n]     = acc[nt][2];
            rw[(c_b + 8) * 33 + n + 1] = acc[nt][3];
        }
        __syncthreads();

        {
            float s0 = 0.0f, s1 = 0.0f;
#pragma unroll
            for (int w = 0; w < 8; w++) {
                s0 += sR[w * 528 + rb * 33 + rn];
                s1 += sR[w * 528 + (rb + 1) * 33 + rn];
            }
            float o0 = tanhf(s0 + e0);
            float o1 = tanhf(s1 + e1);
            size_t m = (size_t)s * 64 + eb;
            g_a[m * 1024 + en]       = __float2half_rn(o0);
            g_a[(m + 1) * 1024 + en] = __float2half_rn(o1);
            if (s == SS - 1) {
                g_hN[(size_t)eb * HH + en]       = o0;
                g_hN[(size_t)(eb + 1) * HH + en] = o1;
            }
        }
        __syncthreads();          // all g_a stores done before release

        if (tid == 0) {
            asm volatile("red.release.gpu.global.add.u32 [%0], %1;"
                         :: "l"(myctr), "r"(1u) : "memory");
        }
        // no trailing barrier/poll: next iteration's distributed poll handles it
    }
}

// ---------------- fc GEMM fp16 K'=1024, 128x128 tile, 2 CTA/SM ----------------
// R8-validated tile/fragment scheme; warp tile 64x32 (acc 64 regs).
#define FC_A_BYTES 10240
#define FC_STAGE   20480
#define FC_SMEM    (FC_STAGE * 3)

__global__ void __launch_bounds__(256, 2) fc_mma_k(const float* __restrict__ fcb,
                                                   float* __restrict__ out) {
    extern __shared__ char dsm[];
    const int tid = threadIdx.x, lane = tid & 31, wid = tid >> 5;
    const int wm = wid & 1, wn = wid >> 1;
    const int n0 = blockIdx.x * 128, m0 = blockIdx.y * 128;
    const uint32_t sbase = smem_u32(dsm);

    float acc[4][4][4];
#pragma unroll
    for (int i = 0; i < 4; i++)
#pragma unroll
        for (int j = 0; j < 4; j++)
#pragma unroll
            for (int q = 0; q < 4; q++) acc[i][j][q] = 0.0f;

    const int lr = tid >> 2, lg = tid & 3;

#define FC_ISSUE(c, st) do {                                                              \
        uint32_t sa = sbase + (st) * FC_STAGE;                                            \
        uint32_t sb = sa + FC_A_BYTES;                                                    \
        const __half* pa = g_a + (size_t)m0 * 1024 + (c) * 32;                            \
        const __half* pb = g_b + (size_t)n0 * 1024 + (c) * 32;                            \
        cpasync16(sa + lr * 80 + lg * 16,        pa + (size_t)lr * 1024 + lg * 8);        \
        cpasync16(sa + (lr + 64) * 80 + lg * 16, pa + (size_t)(lr + 64) * 1024 + lg * 8); \
        cpasync16(sb + lr * 80 + lg * 16,        pb + (size_t)lr * 1024 + lg * 8);        \
        cpasync16(sb + (lr + 64) * 80 + lg * 16, pb + (size_t)(lr + 64) * 1024 + lg * 8); \
    } while (0)

    FC_ISSUE(0, 0); CP_COMMIT();
    FC_ISSUE(1, 1); CP_COMMIT();

    const int arow = wm * 64 + (lane & 15);
    const int agq  = lane >> 4;
    const int brow = wn * 32 + (lane & 7) + ((lane >> 4) << 3);
    const int bgq  = (lane >> 3) & 1;

    for (int c = 0; c < 32; c++) {
        const int st = c % 3;
        CP_WAIT(1);
        __syncthreads();
        if (c + 2 < 32) FC_ISSUE(c + 2, (c + 2) % 3);
        CP_COMMIT();

        uint32_t sa = sbase + st * FC_STAGE;
        uint32_t sb = sa + FC_A_BYTES;
#pragma unroll
        for (int kt = 0; kt < 2; kt++) {
            uint32_t afr[4][4], bfr[2][4];
#pragma unroll
            for (int mt = 0; mt < 4; mt++)
                ldsm4(afr[mt], sa + (uint32_t)((arow + mt * 16) * 80 + (kt * 2 + agq) * 16));
#pragma unroll
            for (int bt = 0; bt < 2; bt++)
                ldsm4(bfr[bt], sb + (uint32_t)((brow + bt * 16) * 80 + (kt * 2 + bgq) * 16));
#pragma unroll
            for (int mt = 0; mt < 4; mt++)
#pragma unroll
                for (int nt = 0; nt < 4; nt++)
                    mma16816(acc[mt][nt], afr[mt], &bfr[nt >> 1][(nt & 1) * 2]);
        }
    }

#pragma unroll
    for (int mt = 0; mt < 4; mt++) {
        int row = m0 + wm * 64 + mt * 16 + (lane >> 2);
#pragma unroll
        for (int nt = 0; nt < 4; nt++) {
            int col = n0 + wn * 32 + nt * 8 + 2 * (lane & 3);
            float2 bias = *(const float2*)(fcb + col);
            float2 v0, v1;
            v0.x = acc[mt][nt][0] + bias.x;
            v0.y = acc[mt][nt][1] + bias.y;
            v1.x = acc[mt][nt][2] + bias.x;
            v1.y = acc[mt][nt][3] + bias.y;
            *(float2*)(out + (size_t)row * VV + col) = v0;
            *(float2*)(out + (size_t)(row + 8) * VV + col) = v1;
        }
    }
}

// ---------------- final state copy --------------------------------------------
__global__ void copy_state_k(float* __restrict__ dst) {
    int j = blockIdx.x * 256 + threadIdx.x;
    if (j < BB * HH) dst[j] = g_hN[j];
}

// ---------------- launch --------------------------------------------------------
extern "C" void kernel_launch(void* const* d_in, const int* in_sizes, int n_in,
                              void* d_out, int out_size) {
    const void*  x     = d_in[0];
    const float* state = (const float*)d_in[1];
    const float* W_ih  = (const float*)d_in[2];
    const float* W_hh  = (const float*)d_in[3];
    const float* b_ih  = (const float*)d_in[4];
    const float* b_hh  = (const float*)d_in[5];
    const float* fc_W  = (const float*)d_in[6];
    const float* fc_b  = (const float*)d_in[7];
    float* out = (float*)d_out;
    (void)in_sizes; (void)n_in; (void)out_size;

    static int attr_set = 0;
    if (!attr_set) {
        cudaFuncSetAttribute(rnn_mma_k,
                             cudaFuncAttributeMaxDynamicSharedMemorySize,
                             RNN_SMEM);
        cudaFuncSetAttribute(fc_mma_k,
                             cudaFuncAttributeMaxDynamicSharedMemorySize,
                             FC_SMEM);
        attr_set = 1;
    }

    detect_k<<<1, 256>>>((const unsigned int*)x);
    transpose_k<<<dim3(VV / 32, HH / 32), dim3(32, 8)>>>(W_ih);
    st0_k<<<256, 256>>>(state);
    embed_k<<<SS * BB, 256>>>(x, b_ih, b_hh);
    conv_w_k<<<VV, 128>>>(fc_W);
    rnn_mma_k<<<128, 256, RNN_SMEM>>>(W_hh);
    fc_mma_k<<<dim3(VV / 128, (SS * BB) / 128), 256, FC_SMEM>>>(fc_b, out);
    copy_state_k<<<256, 256>>>(out + (size_t)SS * BB * VV);
}

// round 15
// speedup vs baseline: 1.2715x; 1.2715x over previous
#include <cuda_runtime.h>
#include <cuda_fp16.h>
#include <cstdint>
#include <math.h>

#define SS 256
#define BB 64
#define HH 1024
#define VV 8192

// ---------------- scratch (device globals; no allocations allowed) ----------
__device__ float g_emb[SS * BB * HH];          // (S,B,H) embeddings + biases
__device__ float g_wih_t[VV * HH];             // W_ih^T: [v][h]
__device__ float g_hN[BB * HH];                // final hidden state fp32 [b][h]
__device__ __half g_h0[BB * HH];               // initial state fp16 [b][h]
__device__ int   g_isI64;
__device__ unsigned int g_ctr4[4 * 32];        // per-b-group counters, 128B apart

// fp16 GEMM images (K' = 1024):
__device__ __half g_a[(size_t)16384 * 1024];   // h fp16 [m=s*64+b][k]; rnn writes, fc reads
__device__ __half g_b[(size_t)8192 * 1024];    // fc_W fp16

typedef unsigned long long u64;

__device__ __forceinline__ uint32_t smem_u32(const void* p) {
    uint32_t a;
    asm("{ .reg .u64 t; cvta.to.shared.u64 t, %1; cvt.u32.u64 %0, t; }" : "=r"(a) : "l"(p));
    return a;
}
__device__ __forceinline__ unsigned pack_h2(float a, float b) {
    __half2 t = __floats2half2_rn(a, b);
    unsigned u;
    memcpy(&u, &t, 4);
    return u;
}
__device__ __forceinline__ void cpasync16(uint32_t dst, const void* src) {
    asm volatile("cp.async.cg.shared.global [%0], [%1], 16;" :: "r"(dst), "l"(src) : "memory");
}
#define CP_COMMIT() asm volatile("cp.async.commit_group;" ::: "memory")
#define CP_WAIT(n)  asm volatile("cp.async.wait_group %0;" :: "n"(n) : "memory")

__device__ __forceinline__ void ldsm4(uint32_t* r, uint32_t addr) {
    asm volatile("ldmatrix.sync.aligned.m8n8.x4.shared.b16 {%0,%1,%2,%3}, [%4];"
                 : "=r"(r[0]), "=r"(r[1]), "=r"(r[2]), "=r"(r[3]) : "r"(addr));
}
__device__ __forceinline__ void mma16816(float* c, const uint32_t* a, const uint32_t* b) {
    asm volatile(
        "mma.sync.aligned.m16n8k16.row.col.f32.f16.f16.f32 "
        "{%0,%1,%2,%3}, {%4,%5,%6,%7}, {%8,%9}, {%0,%1,%2,%3};"
        : "+f"(c[0]), "+f"(c[1]), "+f"(c[2]), "+f"(c[3])
        : "r"(a[0]), "r"(a[1]), "r"(a[2]), "r"(a[3]), "r"(b[0]), "r"(b[1]));
}
__device__ __forceinline__ unsigned ld_acq(const unsigned int* p) {
    unsigned v;
    asm volatile("ld.acquire.gpu.global.u32 %0, [%1];" : "=r"(v) : "l"(p) : "memory");
    return v;
}

// ---------------- dtype detection --------------------------------------------
__global__ void detect_k(const unsigned int* __restrict__ xw) {
    __shared__ unsigned int red[256];
    unsigned int v = 0;
    for (int i = threadIdx.x; i < 8192; i += 256) v |= xw[2 * i + 1];
    red[threadIdx.x] = v;
    __syncthreads();
    for (int st = 128; st > 0; st >>= 1) {
        if (threadIdx.x < st) red[threadIdx.x] |= red[threadIdx.x + st];
        __syncthreads();
    }
    if (threadIdx.x == 0) g_isI64 = (red[0] == 0u) ? 1 : 0;
}

// ---------------- W_ih transpose ----------------------------------------------
__global__ void transpose_k(const float* __restrict__ in) {
    __shared__ float t[32][33];
    const int R = HH, C = VV;
    int c0 = blockIdx.x * 32, r0 = blockIdx.y * 32;
#pragma unroll
    for (int i = 0; i < 32; i += 8)
        t[threadIdx.y + i][threadIdx.x] =
            in[(size_t)(r0 + threadIdx.y + i) * C + c0 + threadIdx.x];
    __syncthreads();
#pragma unroll
    for (int i = 0; i < 32; i += 8)
        g_wih_t[(size_t)(c0 + threadIdx.y + i) * R + r0 + threadIdx.x] =
            t[threadIdx.x][threadIdx.y + i];
}

// ---------------- init ----------------------------------------------------------
__global__ void st0_k(const float* __restrict__ state) {
    int j = blockIdx.x * 256 + threadIdx.x;
    if (j < BB * HH) g_h0[j] = __float2half_rn(state[j]);
    if (j < 4 * 32) g_ctr4[j] = 0u;
}

// ---------------- embedding gather + bias fold --------------------------------
__global__ void embed_k(const void* __restrict__ xraw,
                        const float* __restrict__ b_ih,
                        const float* __restrict__ b_hh) {
    int sb = blockIdx.x;
    int b = sb & (BB - 1);
    int s = sb >> 6;
    const int* xi = (const int*)xraw;
    long long pos = (long long)b * SS + s;
    int idx = g_isI64 ? xi[2 * pos] : xi[pos];
    int h4 = threadIdx.x * 4;
    float4 w  = *(const float4*)(g_wih_t + (size_t)idx * HH + h4);
    float4 bi = *(const float4*)(b_ih + h4);
    float4 bh = *(const float4*)(b_hh + h4);
    float4 o;
    o.x = w.x + bi.x + bh.x;
    o.y = w.y + bi.y + bh.y;
    o.z = w.z + bi.z + bh.z;
    o.w = w.w + bi.w + bh.w;
    *(float4*)(g_emb + (size_t)sb * HH + h4) = o;
}

// ---------------- conv_w: fc_W -> B fp16 ---------------------------------------
__global__ void conv_w_k(const float* __restrict__ fcW) {
    const int v = blockIdx.x;
    const int t = threadIdx.x;
    const float4* s4 = (const float4*)(fcW + (size_t)v * HH + t * 8);
    float4 va = s4[0], vb = s4[1];
    unsigned hx[4];
    hx[0] = pack_h2(va.x, va.y);
    hx[1] = pack_h2(va.z, va.w);
    hx[2] = pack_h2(vb.x, vb.y);
    hx[3] = pack_h2(vb.z, vb.w);
    *(uint4*)(g_b + (size_t)v * 1024 + t * 8) = make_uint4(hx[0], hx[1], hx[2], hx[3]);
}

// ---------------- persistent recurrence via tensor cores ----------------------
// R12 structure; sync change ONLY: head poll with nanosleep backoff replaces
// tail tid0-poll+BAR (3 bar.sync/step -> 2).
#define RNN_SW_B  66048
#define RNN_SA_B  34816
#define RNN_SR_F  (8 * 528)
#define RNN_SMEM  (RNN_SW_B + RNN_SA_B + RNN_SR_F * 4)

__global__ void __launch_bounds__(256, 1) rnn_mma_k(const float* __restrict__ W_hh) {
    extern __shared__ char smraw[];
    const uint32_t sW0 = smem_u32(smraw);
    const uint32_t sA0 = sW0 + RNN_SW_B;
    float* sR = (float*)(smraw + RNN_SW_B + RNN_SA_B);

    const int tid = threadIdx.x, cta = blockIdx.x;
    const int lane = tid & 31;
    const int kh   = tid >> 5;
    const int bi = cta >> 5;
    const int n0 = (cta & 31) * 32;
    const int bbase = bi * 16;
    const unsigned int* myctr = &g_ctr4[bi * 32];

    {
        int nrow = tid >> 3, kseg = (tid & 7) * 128;
        const float* wsrc = W_hh + (size_t)(n0 + nrow) * HH + kseg;
        uint32_t wdst = sW0 + (uint32_t)nrow * 2064 + (uint32_t)kseg * 2;
#pragma unroll
        for (int j = 0; j < 16; j++) {
            float4 w1 = *(const float4*)(wsrc + j * 8);
            float4 w2 = *(const float4*)(wsrc + j * 8 + 4);
            uint4 hv = make_uint4(pack_h2(w1.x, w1.y), pack_h2(w1.z, w1.w),
                                  pack_h2(w2.x, w2.y), pack_h2(w2.z, w2.w));
            asm volatile("st.shared.v4.b32 [%0], {%1,%2,%3,%4};"
                         :: "r"(wdst + j * 16), "r"(hv.x), "r"(hv.y), "r"(hv.z), "r"(hv.w)
                         : "memory");
        }
    }
    __syncthreads();

    const int arow = lane & 15;
    const int agq  = lane >> 4;
    const int brow = (lane & 7) + ((lane >> 4) << 3);
    const int bgq  = (lane >> 3) & 1;
    const uint32_t sAw = sA0 + (uint32_t)kh * 4352;

    const int c_b = lane >> 2;
    const int c_n = 2 * (lane & 3);

    const int rn = tid >> 3;
    const int rb = (tid & 7) * 2;
    const int en = n0 + rn;
    const int eb = bbase + rb;

    for (int s = 0; s < SS; s++) {
        // emb prefetch (counter-independent)
        const float* es = g_emb + (size_t)s * BB * HH;
        float e0 = es[(size_t)eb * HH + en];
        float e1 = es[(size_t)(eb + 1) * HH + en];

        // head poll with backoff: wait until all 32 group CTAs published step s-1
        if (s > 0) {
            unsigned target = 32u * (unsigned)s;
            while (ld_acq(myctr) < target) __nanosleep(64);
        }

        const __half* hsrc = (s == 0) ? (g_h0 + (size_t)bbase * HH)
                                      : (g_a + ((size_t)(s - 1) * 64 + bbase) * 1024);
#pragma unroll
        for (int i = 0; i < 8; i++) {
            int id = i * 32 + lane;
            int row = id >> 4, c16 = id & 15;
            cpasync16(sAw + (uint32_t)(row * 272 + c16 * 16),
                      hsrc + (size_t)row * 1024 + kh * 128 + c16 * 8);
        }
        CP_COMMIT();
        CP_WAIT(0);
        __syncwarp();

        float acc[4][4];
#pragma unroll
        for (int i = 0; i < 4; i++)
#pragma unroll
            for (int q = 0; q < 4; q++) acc[i][q] = 0.0f;

#pragma unroll
        for (int kt = 0; kt < 8; kt++) {
            uint32_t afr[4], bfr[2][4];
            ldsm4(afr, sAw + (uint32_t)(arow * 272 + kt * 32 + agq * 16));
#pragma unroll
            for (int bt = 0; bt < 2; bt++)
                ldsm4(bfr[bt], sW0 + (uint32_t)((brow + bt * 16) * 2064
                                                + kh * 256 + kt * 32 + bgq * 16));
#pragma unroll
            for (int nt = 0; nt < 4; nt++)
                mma16816(acc[nt], afr, &bfr[nt >> 1][(nt & 1) * 2]);
        }

        float* rw = sR + kh * 528;
#pragma unroll
        for (int nt = 0; nt < 4; nt++) {
            int n = nt * 8 + c_n;
            rw[c_b * 33 + n]           = acc[nt][0];
            rw[c_b * 33 + n + 1]       = acc[nt][1];
            rw[(c_b + 8) * 33 + n]     = acc[nt][2];
            rw[(c_b + 8) * 33 + n + 1] = acc[nt][3];
        }
        __syncthreads();

        {
            float s0 = 0.0f, s1 = 0.0f;
#pragma unroll
            for (int w = 0; w < 8; w++) {
                s0 += sR[w * 528 + rb * 33 + rn];
                s1 += sR[w * 528 + (rb + 1) * 33 + rn];
            }
            float o0 = tanhf(s0 + e0);
            float o1 = tanhf(s1 + e1);
            size_t m = (size_t)s * 64 + eb;
            g_a[m * 1024 + en]       = __float2half_rn(o0);
            g_a[(m + 1) * 1024 + en] = __float2half_rn(o1);
            if (s == SS - 1) {
                g_hN[(size_t)eb * HH + en]       = o0;
                g_hN[(size_t)(eb + 1) * HH + en] = o1;
            }
        }
        __syncthreads();          // all g_a stores complete before release

        if (tid == 0) {
            asm volatile("red.release.gpu.global.add.u32 [%0], %1;"
                         :: "l"(myctr), "r"(1u) : "memory");
        }
    }
}

// ---------------- fc GEMM fp16 K'=1024 (R9 proven verbatim) -------------------
#define FC_A_BYTES 10240
#define FC_STAGE   30720
#define FC_SMEM    (FC_STAGE * 3)

__global__ void __launch_bounds__(256, 1) fc_mma_k(const float* __restrict__ fcb,
                                                   float* __restrict__ out) {
    extern __shared__ char dsm[];
    const int tid = threadIdx.x, lane = tid & 31, wid = tid >> 5;
    const int wm = wid & 1, wn = wid >> 1;
    const int n0 = blockIdx.x * 256, m0 = blockIdx.y * 128;
    const uint32_t sbase = smem_u32(dsm);

    float acc[4][8][4];
#pragma unroll
    for (int i = 0; i < 4; i++)
#pragma unroll
        for (int j = 0; j < 8; j++)
#pragma unroll
            for (int q = 0; q < 4; q++) acc[i][j][q] = 0.0f;

    const int lr = tid >> 2, lg = tid & 3;

#define FC_ISSUE(c, st) do {                                                              \
        uint32_t sa = sbase + (st) * FC_STAGE;                                            \
        uint32_t sb = sa + FC_A_BYTES;                                                    \
        const __half* pa = g_a + (size_t)m0 * 1024 + (c) * 32;                            \
        const __half* pb = g_b + (size_t)n0 * 1024 + (c) * 32;                            \
        cpasync16(sa + lr * 80 + lg * 16,          pa + (size_t)lr * 1024 + lg * 8);          \
        cpasync16(sa + (lr + 64) * 80 + lg * 16,   pa + (size_t)(lr + 64) * 1024 + lg * 8);   \
        cpasync16(sb + lr * 80 + lg * 16,          pb + (size_t)lr * 1024 + lg * 8);          \
        cpasync16(sb + (lr + 64) * 80 + lg * 16,   pb + (size_t)(lr + 64) * 1024 + lg * 8);   \
        cpasync16(sb + (lr + 128) * 80 + lg * 16,  pb + (size_t)(lr + 128) * 1024 + lg * 8);  \
        cpasync16(sb + (lr + 192) * 80 + lg * 16,  pb + (size_t)(lr + 192) * 1024 + lg * 8);  \
    } while (0)

    FC_ISSUE(0, 0); CP_COMMIT();
    FC_ISSUE(1, 1); CP_COMMIT();

    const int arow = wm * 64 + (lane & 15);
    const int agq  = lane >> 4;
    const int brow = wn * 64 + (lane & 7) + ((lane >> 4) << 3);
    const int bgq  = (lane >> 3) & 1;

    for (int c = 0; c < 32; c++) {
        const int st = c % 3;
        CP_WAIT(1);
        __syncthreads();
        if (c + 2 < 32) FC_ISSUE(c + 2, (c + 2) % 3);
        CP_COMMIT();

        uint32_t sa = sbase + st * FC_STAGE;
        uint32_t sb = sa + FC_A_BYTES;
#pragma unroll
        for (int kt = 0; kt < 2; kt++) {
            uint32_t afr[4][4], bfr[4][4];
#pragma unroll
            for (int mt = 0; mt < 4; mt++)
                ldsm4(afr[mt], sa + (uint32_t)((arow + mt * 16) * 80 + (kt * 2 + agq) * 16));
#pragma unroll
            for (int bt = 0; bt < 4; bt++)
                ldsm4(bfr[bt], sb + (uint32_t)((brow + bt * 16) * 80 + (kt * 2 + bgq) * 16));
#pragma unroll
            for (int mt = 0; mt < 4; mt++)
#pragma unroll
                for (int nt = 0; nt < 8; nt++)
                    mma16816(acc[mt][nt], afr[mt], &bfr[nt >> 1][(nt & 1) * 2]);
        }
    }

#pragma unroll
    for (int mt = 0; mt < 4; mt++) {
        int row = m0 + wm * 64 + mt * 16 + (lane >> 2);
#pragma unroll
        for (int nt = 0; nt < 8; nt++) {
            int col = n0 + wn * 64 + nt * 8 + 2 * (lane & 3);
            float2 bias = *(const float2*)(fcb + col);
            float2 v0, v1;
            v0.x = acc[mt][nt][0] + bias.x;
            v0.y = acc[mt][nt][1] + bias.y;
            v1.x = acc[mt][nt][2] + bias.x;
            v1.y = acc[mt][nt][3] + bias.y;
            *(float2*)(out + (size_t)row * VV + col) = v0;
            *(float2*)(out + (size_t)(row + 8) * VV + col) = v1;
        }
    }
}

// ---------------- final state copy --------------------------------------------
__global__ void copy_state_k(float* __restrict__ dst) {
    int j = blockIdx.x * 256 + threadIdx.x;
    if (j < BB * HH) dst[j] = g_hN[j];
}

// ---------------- launch --------------------------------------------------------
extern "C" void kernel_launch(void* const* d_in, const int* in_sizes, int n_in,
                              void* d_out, int out_size) {
    const void*  x     = d_in[0];
    const float* state = (const float*)d_in[1];
    const float* W_ih  = (const float*)d_in[2];
    const float* W_hh  = (const float*)d_in[3];
    const float* b_ih  = (const float*)d_in[4];
    const float* b_hh  = (const float*)d_in[5];
    const float* fc_W  = (const float*)d_in[6];
    const float* fc_b  = (const float*)d_in[7];
    float* out = (float*)d_out;
    (void)in_sizes; (void)n_in; (void)out_size;

    static int attr_set = 0;
    if (!attr_set) {
        cudaFuncSetAttribute(rnn_mma_k,
                             cudaFuncAttributeMaxDynamicSharedMemorySize,
                             RNN_SMEM);
        cudaFuncSetAttribute(fc_mma_k,
                             cudaFuncAttributeMaxDynamicSharedMemorySize,
                             FC_SMEM);
        attr_set = 1;
    }

    detect_k<<<1, 256>>>((const unsigned int*)x);
    transpose_k<<<dim3(VV / 32, HH / 32), dim3(32, 8)>>>(W_ih);
    st0_k<<<256, 256>>>(state);
    embed_k<<<SS * BB, 256>>>(x, b_ih, b_hh);
    conv_w_k<<<VV, 128>>>(fc_W);
    rnn_mma_k<<<128, 256, RNN_SMEM>>>(W_hh);
    fc_mma_k<<<dim3(VV / 256, (SS * BB) / 128), 256, FC_SMEM>>>(fc_b, out);
    copy_state_k<<<256, 256>>>(out + (size_t)SS * BB * VV);
}